// round 7
// baseline (speedup 1.0000x reference)
#include <cuda_runtime.h>
#include <math.h>

#define SS 128
#define BB 64
#define VV 32000
#define EHH 512
#define EOO 512
#define HH 1024
#define G3 3072
#define TOK (SS*BB)   // 8192
#define NB 128        // persistent blocks
#define GNT 1024      // gru threads per block

// ---------------- scratch (no allocations allowed) ----------------
__device__ float g_emb[TOK*EHH];          // 16 MB
__device__ float g_x[TOK*EOO];            // 16 MB
__device__ float g_xw[(size_t)TOK*G3];    // 96 MB, layout [S][3H][B]
__device__ float g_h[2][HH*BB];           // transposed: h[j][b]
__device__ __align__(128) unsigned g_leaf[16*32];  // tree barrier leaves
__device__ unsigned g_root;
__device__ volatile unsigned g_gen;

// ---------------- f32x2 helpers ----------------
__device__ __forceinline__ unsigned long long ffma2(unsigned long long a,
                                                    unsigned long long b,
                                                    unsigned long long c)
{
    unsigned long long d;
    asm("fma.rn.f32x2 %0, %1, %2, %3;" : "=l"(d) : "l"(a), "l"(b), "l"(c));
    return d;
}
__device__ __forceinline__ unsigned long long splat2(float x)
{
    unsigned long long d;
    asm("mov.b64 %0, {%1, %1};" : "=l"(d) : "r"(__float_as_uint(x)));
    return d;
}
__device__ __forceinline__ float2 unpack2(unsigned long long v)
{
    float2 r;
    asm("mov.b64 {%0, %1}, %2;" : "=f"(r.x), "=f"(r.y) : "l"(v));
    return r;
}

// ---------------- 1) embedding gather + bias + threshold ----------------
__global__ void emb_kernel(const int* __restrict__ ids,
                           const float* __restrict__ W1,
                           const float* __restrict__ b1)
{
    int tok = blockIdx.x;
    int id  = ids[tok];
    for (int e = threadIdx.x; e < EHH; e += blockDim.x) {
        float v = W1[(size_t)e * VV + id] + b1[e];
        g_emb[(size_t)tok * EHH + e] = (v > 1e-6f) ? v : 0.0f;
    }
}

// ---------------- 2) tiled SGEMM (f32x2): C = act(A @ Bw^T + bias) --------
// TRANSOUT=1: write C_t[s][n][b] (b = m&63, s = m>>6) for the GRU gate path.
template<int ACT, int TRANSOUT>
__global__ void __launch_bounds__(256)
gemm_nt_act(const float* __restrict__ A, const float* __restrict__ Bw,
            const float* __restrict__ bias, float* __restrict__ C,
            int M, int N, int K)
{
    __shared__ float As[8][132];
    __shared__ float Bs[8][132];
    const int tid = threadIdx.x;
    const int bm = blockIdx.y * 128;
    const int bn = blockIdx.x * 128;
    const int lr = tid >> 1;
    const int lc = (tid & 1) * 4;
    const int ty = tid >> 4;
    const int tx = tid & 15;

    unsigned long long acc2[4][8];
    #pragma unroll
    for (int i = 0; i < 4; i++)
        #pragma unroll
        for (int j = 0; j < 8; j++) acc2[i][j] = 0ULL;

    const float* Ap = A  + (size_t)(bm + lr) * K + lc;
    const float* Bp = Bw + (size_t)(bn + lr) * K + lc;

    for (int k0 = 0; k0 < K; k0 += 8) {
        float4 av = *(const float4*)(Ap + k0);
        float4 bv = *(const float4*)(Bp + k0);
        As[lc+0][lr] = av.x; As[lc+1][lr] = av.y;
        As[lc+2][lr] = av.z; As[lc+3][lr] = av.w;
        Bs[lc+0][lr] = bv.x; Bs[lc+1][lr] = bv.y;
        Bs[lc+2][lr] = bv.z; Bs[lc+3][lr] = bv.w;
        __syncthreads();
        #pragma unroll
        for (int kk = 0; kk < 8; kk++) {
            ulonglong2 A01 = *(const ulonglong2*)&As[kk][ty*8];
            ulonglong2 A23 = *(const ulonglong2*)&As[kk][ty*8+4];
            float4 b0 = *(const float4*)&Bs[kk][tx*8];
            float4 b1 = *(const float4*)&Bs[kk][tx*8+4];
            unsigned long long a2[4] = {A01.x, A01.y, A23.x, A23.y};
            unsigned long long bsp[8] = {
                splat2(b0.x), splat2(b0.y), splat2(b0.z), splat2(b0.w),
                splat2(b1.x), splat2(b1.y), splat2(b1.z), splat2(b1.w)};
            #pragma unroll
            for (int i2 = 0; i2 < 4; i2++)
                #pragma unroll
                for (int j = 0; j < 8; j++)
                    acc2[i2][j] = ffma2(a2[i2], bsp[j], acc2[i2][j]);
        }
        __syncthreads();
    }

    #pragma unroll
    for (int i2 = 0; i2 < 4; i2++) {
        int m0 = bm + ty*8 + i2*2;       // even
        #pragma unroll
        for (int j = 0; j < 8; j++) {
            int n = bn + tx*8 + j;
            float2 v = unpack2(acc2[i2][j]);
            float bb = bias[n];
            float v0 = v.x + bb, v1 = v.y + bb;
            if (ACT) { v0 = (v0 > 1e-6f) ? v0 : 0.0f;
                       v1 = (v1 > 1e-6f) ? v1 : 0.0f; }
            if (TRANSOUT) {
                int s = m0 >> 6, b0 = m0 & 63;   // m0 even -> m0,m0+1 same s
                float2 p; p.x = v0; p.y = v1;
                *(float2*)&C[((size_t)s * N + n) * 64 + b0] = p;
            } else {
                C[(size_t)m0     * N + n] = v0;
                C[(size_t)(m0+1) * N + n] = v1;
            }
        }
    }
}

// ---------------- tree grid barrier (2-level, graph-replay safe) ----------
__device__ __forceinline__ void grid_bar()
{
    __threadfence();
    __syncthreads();
    if (threadIdx.x == 0) {
        unsigned my = g_gen;
        int leaf = blockIdx.x & 15;               // 16 leaves x 8 blocks
        bool done = false;
        if (atomicAdd(&g_leaf[leaf*32], 1) == 7) {
            g_leaf[leaf*32] = 0;
            __threadfence();
            if (atomicAdd(&g_root, 1) == 15) {
                g_root = 0;
                __threadfence();
                g_gen = my + 1;
                done = true;
            }
        }
        if (!done) { while (g_gen == my) { } }
    }
    __syncthreads();
}

// ---------------- 3) persistent GRU recurrence ----------------------------
// 128 blocks x 1024 threads (32 warps/SM, 1 block/SM via smem). Block owns
// 8 h-columns = 24 W_hh rows in smem (stride-32 rows: LDS.128 w-triples).
// 8 k-groups x 128 threads; per group: 8 k-tiles of 16, double-buffered
// LDG.128->STS.128 staging, per-group named barriers. Each thread: 4
// batches x 3 gate-cols, f32x2 FMAs. xw is [S][3H][B] -> coalesced gates.
#define WSM_F   (1024*32)          // Wsm[k*32 + tc*4 + j]
#define HSS_F   (2*8*16*68)        // Hs[buf][g][k][b] = 17408 floats
#define SMEM_BYTES ((WSM_F + HSS_F) * 4)   // 200704 B

__global__ void __launch_bounds__(GNT, 1)
gru_persist(const float* __restrict__ W_hh, const float* __restrict__ b_hh,
            const float* __restrict__ xw, float* __restrict__ hbuf)
{
    extern __shared__ float smf[];
    float* Wsm = smf;                    // 32768 floats
    float* Hss = smf + WSM_F;            // 17408 floats
    float* red = Hss;                    // alias: 8*1600 = 12800 floats

    const int tid = threadIdx.x;
    const int g   = tid >> 7;            // k-group 0..7 (128 k each)
    const int t   = tid & 127;
    const int tb  = t >> 3;              // batch-group 0..15 (4 batches)
    const int tc  = t & 7;               // c-group 0..7 (c = tc*3+j)
    const int j0  = blockIdx.x * 8;

    // cache W_hh slice: Wsm[k*32 + (c/3)*4 + c%3]
    for (int idx = tid; idx < 24*1024; idx += GNT) {
        int c = idx >> 10, k = idx & 1023;
        int grow = (c >> 3) * HH + j0 + (c & 7);
        Wsm[k*32 + (c/3)*4 + (c%3)] = W_hh[(size_t)grow * HH + k];
    }

    // gate-phase mapping (tid < 512): jj slow, bb fast -> coalesced
    const int jj   = (tid >> 6) & 7;
    const int bb   = tid & 63;
    const int jcol = j0 + jj;
    float bhr = 0.f, bhz = 0.f, bhn = 0.f;
    if (tid < 512) {
        bhr = b_hh[jcol];
        bhz = b_hh[HH + jcol];
        bhn = b_hh[2*HH + jcol];
    }
    __syncthreads();

    for (int s = 0; s < SS; s++) {
        const float* h_in  = hbuf + (s & 1) * (HH*BB);
        float*       h_out = hbuf + ((s + 1) & 1) * (HH*BB);
        const float* xws   = xw + (size_t)s * G3 * BB;   // [3H][B]

        float xr = 0.f, xz = 0.f, xn = 0.f;
        float hp = 0.f, gr = 0.f, gz = 0.f, gn = 0.f;

        if (s > 0) {
            unsigned long long acc2[2][3];
            #pragma unroll
            for (int i = 0; i < 2; i++)
                #pragma unroll
                for (int j = 0; j < 3; j++) acc2[i][j] = 0ULL;

            // prologue: prefetch kt=0 tile (coalesced: h_in is [k][b])
            float4 pre[2];
            {
                int kb = g * 128;
                #pragma unroll
                for (int r = 0; r < 2; r++) {
                    int f = t + 128*r;           // 0..255
                    int k = kb + (f >> 4), b4 = (f & 15) * 4;
                    pre[r] = __ldcg((const float4*)&h_in[(size_t)k*BB + b4]);
                }
            }

            for (int kt = 0; kt < 8; kt++) {
                float* Hbuf = Hss + (((kt & 1) * 8 + g) * 16) * 68;
                #pragma unroll
                for (int r = 0; r < 2; r++) {
                    int f = t + 128*r;
                    int kk2 = f >> 4, b4 = (f & 15) * 4;
                    *(float4*)&Hbuf[kk2*68 + b4] = pre[r];
                }
                asm volatile("bar.sync %0, 128;" :: "r"(1 + g) : "memory");
                if (kt < 7) {
                    int kb = g * 128 + (kt + 1) * 16;
                    #pragma unroll
                    for (int r = 0; r < 2; r++) {
                        int f = t + 128*r;
                        int k = kb + (f >> 4), b4 = (f & 15) * 4;
                        pre[r] = __ldcg((const float4*)&h_in[(size_t)k*BB + b4]);
                    }
                }
                const float* wbase = Wsm + (g*128 + kt*16) * 32 + tc*4;
                #pragma unroll
                for (int kk = 0; kk < 16; kk++) {
                    const float* hrow = Hbuf + kk*68;
                    ulonglong2 hA = *(const ulonglong2*)&hrow[tb*4];
                    float4 wv = *(const float4*)(wbase + kk*32);
                    unsigned long long w0 = splat2(wv.x);
                    unsigned long long w1 = splat2(wv.y);
                    unsigned long long w2 = splat2(wv.z);
                    acc2[0][0] = ffma2(hA.x, w0, acc2[0][0]);
                    acc2[0][1] = ffma2(hA.x, w1, acc2[0][1]);
                    acc2[0][2] = ffma2(hA.x, w2, acc2[0][2]);
                    acc2[1][0] = ffma2(hA.y, w0, acc2[1][0]);
                    acc2[1][1] = ffma2(hA.y, w1, acc2[1][1]);
                    acc2[1][2] = ffma2(hA.y, w2, acc2[1][2]);
                }
            }

            // gate-input prefetch (coalesced; covered by reduce phase)
            if (tid < 512) {
                xr = __ldg(&xws[(size_t)jcol*BB + bb]);
                xz = __ldg(&xws[(size_t)(HH + jcol)*BB + bb]);
                xn = __ldg(&xws[(size_t)(2*HH + jcol)*BB + bb]);
                hp = __ldcg(&h_in[(size_t)jcol*BB + bb]);
            }

            // parallel 8-way tree reduction (partials alias Hss)
            __syncthreads();   // all groups done with Hss; reusable
            {
                float* myred = red + g * 1600;
                #pragma unroll
                for (int i2 = 0; i2 < 2; i2++) {
                    int b = tb*4 + i2*2;
                    #pragma unroll
                    for (int j = 0; j < 3; j++) {
                        float2 v = unpack2(acc2[i2][j]);
                        int c = tc*3 + j;
                        myred[b*25 + c]     = v.x;
                        myred[(b+1)*25 + c] = v.y;
                    }
                }
            }
            __syncthreads();
            for (int o = tid; o < 1600; o += GNT) {
                float sum = red[o];
                #pragma unroll
                for (int gg = 1; gg < 8; gg++) sum += red[gg*1600 + o];
                red[o] = sum;
            }
            __syncthreads();
            if (tid < 512) {
                gr = red[bb*25 + jj];
                gz = red[bb*25 + 8 + jj];
                gn = red[bb*25 + 16 + jj];
            }
        } else {
            if (tid < 512) {
                xr = __ldg(&xws[(size_t)jcol*BB + bb]);
                xz = __ldg(&xws[(size_t)(HH + jcol)*BB + bb]);
                xn = __ldg(&xws[(size_t)(2*HH + jcol)*BB + bb]);
            }
        }

        // fused gates + h update (coalesced transposed store)
        if (tid < 512) {
            float r = 1.0f / (1.0f + __expf(-(xr + gr + bhr)));
            float z = 1.0f / (1.0f + __expf(-(xz + gz + bhz)));
            float n = tanhf(xn + r * (gn + bhn));
            __stcg(&h_out[(size_t)jcol*BB + bb], (1.0f - z) * n + z * hp);
        }

        grid_bar();
    }
}

// ---------------- 4) final linear: out[b][n] = sum_k h[k][b]*Wo[n][k] -----
__global__ void __launch_bounds__(256)
out_kernel(const float* __restrict__ h /* [HH][BB] */,
           const float* __restrict__ Wo,
           const float* __restrict__ bo, float* __restrict__ out)
{
    __shared__ float hs[8][1032];        // [bb][k], padded stride
    const int b0 = blockIdx.x * 8;
    const int n0 = blockIdx.y * 8;
    const int tid = threadIdx.x;

    for (int idx = tid; idx < 8192; idx += 256) {
        int k = idx >> 3, bb = idx & 7;
        hs[bb][k] = h[(size_t)k*BB + b0 + bb];
    }
    __syncthreads();

    const int w = tid >> 5, lane = tid & 31;
    const int n = n0 + w;
    float acc[8] = {0,0,0,0,0,0,0,0};
    for (int k = lane*4; k < 1024; k += 128) {
        float4 wv = *(const float4*)&Wo[(size_t)n*HH + k];
        #pragma unroll
        for (int bb = 0; bb < 8; bb++) {
            float4 hv = *(const float4*)&hs[bb][k];
            acc[bb] += wv.x*hv.x + wv.y*hv.y + wv.z*hv.z + wv.w*hv.w;
        }
    }
    #pragma unroll
    for (int bb = 0; bb < 8; bb++) {
        float v = acc[bb];
        v += __shfl_down_sync(0xffffffffu, v, 16);
        v += __shfl_down_sync(0xffffffffu, v, 8);
        v += __shfl_down_sync(0xffffffffu, v, 4);
        v += __shfl_down_sync(0xffffffffu, v, 2);
        v += __shfl_down_sync(0xffffffffu, v, 1);
        if (lane == 0) out[(size_t)(b0+bb)*1024 + n] = v + bo[n];
    }
}

// ---------------- launch ----------------
extern "C" void kernel_launch(void* const* d_in, const int* in_sizes, int n_in,
                              void* d_out, int out_size)
{
    const int*   ids   = (const int*)  d_in[0];
    const float* W1    = (const float*)d_in[1];
    const float* b1    = (const float*)d_in[2];
    const float* W2    = (const float*)d_in[3];
    const float* b2    = (const float*)d_in[4];
    const float* W_ih  = (const float*)d_in[5];
    const float* b_ih  = (const float*)d_in[6];
    const float* W_hh  = (const float*)d_in[7];
    const float* b_hh  = (const float*)d_in[8];
    const float* W_out = (const float*)d_in[9];
    const float* b_out = (const float*)d_in[10];
    float* out = (float*)d_out;

    float* emb;  cudaGetSymbolAddress((void**)&emb,  g_emb);
    float* x;    cudaGetSymbolAddress((void**)&x,    g_x);
    float* xw;   cudaGetSymbolAddress((void**)&xw,   g_xw);
    float* hbuf; cudaGetSymbolAddress((void**)&hbuf, g_h);

    static int smem_set = 0;
    if (!smem_set) {
        cudaFuncSetAttribute(gru_persist,
                             cudaFuncAttributeMaxDynamicSharedMemorySize,
                             SMEM_BYTES);
        smem_set = 1;
    }

    emb_kernel<<<TOK, 128>>>(ids, W1, b1);

    gemm_nt_act<1,0><<<dim3(EOO/128, TOK/128), 256>>>(emb, W2, b2, x, TOK, EOO, EHH);
    gemm_nt_act<0,1><<<dim3(G3/128,  TOK/128), 256>>>(x, W_ih, b_ih, xw, TOK, G3, EOO);

    gru_persist<<<NB, GNT, SMEM_BYTES>>>(W_hh, b_hh, xw, hbuf);

    out_kernel<<<dim3(8, 128), 256>>>(hbuf, W_out, b_out, out);
}

// round 8
// speedup vs baseline: 1.0004x; 1.0004x over previous
#include <cuda_runtime.h>
#include <math.h>

#define SS 128
#define BB 64
#define VV 32000
#define EHH 512
#define EOO 512
#define HH 1024
#define G3 3072
#define TOK (SS*BB)   // 8192
#define NB 128        // persistent blocks
#define GNT 1024      // gru threads per block

// ---------------- scratch (no allocations allowed) ----------------
__device__ float g_emb[TOK*EHH];          // 16 MB
__device__ float g_x[TOK*EOO];            // 16 MB
__device__ float g_xw[(size_t)TOK*G3];    // 96 MB, layout [S][3H][B]
__device__ float g_h[2][HH*BB];           // transposed: h[j][b]
__device__ __align__(128) unsigned g_leaf[16*32];  // tree barrier leaves
__device__ unsigned g_root;
__device__ volatile unsigned g_gen;

// ---------------- f32x2 helpers ----------------
__device__ __forceinline__ unsigned long long ffma2(unsigned long long a,
                                                    unsigned long long b,
                                                    unsigned long long c)
{
    unsigned long long d;
    asm("fma.rn.f32x2 %0, %1, %2, %3;" : "=l"(d) : "l"(a), "l"(b), "l"(c));
    return d;
}
__device__ __forceinline__ unsigned long long splat2(float x)
{
    unsigned long long d;
    asm("mov.b64 %0, {%1, %1};" : "=l"(d) : "r"(__float_as_uint(x)));
    return d;
}
__device__ __forceinline__ float2 unpack2(unsigned long long v)
{
    float2 r;
    asm("mov.b64 {%0, %1}, %2;" : "=f"(r.x), "=f"(r.y) : "l"(v));
    return r;
}

// ---------------- 1) embedding gather + bias + threshold ----------------
__global__ void emb_kernel(const int* __restrict__ ids,
                           const float* __restrict__ W1,
                           const float* __restrict__ b1)
{
    int tok = blockIdx.x;
    int id  = ids[tok];
    for (int e = threadIdx.x; e < EHH; e += blockDim.x) {
        float v = W1[(size_t)e * VV + id] + b1[e];
        g_emb[(size_t)tok * EHH + e] = (v > 1e-6f) ? v : 0.0f;
    }
}

// ---------------- 2) tiled SGEMM (f32x2): C = act(A @ Bw^T + bias) --------
// TRANSOUT=1: write C_t[s][n][b] (b = m&63, s = m>>6) for the GRU gate path.
template<int ACT, int TRANSOUT>
__global__ void __launch_bounds__(256)
gemm_nt_act(const float* __restrict__ A, const float* __restrict__ Bw,
            const float* __restrict__ bias, float* __restrict__ C,
            int M, int N, int K)
{
    __shared__ float As[8][132];
    __shared__ float Bs[8][132];
    const int tid = threadIdx.x;
    const int bm = blockIdx.y * 128;
    const int bn = blockIdx.x * 128;
    const int lr = tid >> 1;
    const int lc = (tid & 1) * 4;
    const int ty = tid >> 4;
    const int tx = tid & 15;

    unsigned long long acc2[4][8];
    #pragma unroll
    for (int i = 0; i < 4; i++)
        #pragma unroll
        for (int j = 0; j < 8; j++) acc2[i][j] = 0ULL;

    const float* Ap = A  + (size_t)(bm + lr) * K + lc;
    const float* Bp = Bw + (size_t)(bn + lr) * K + lc;

    for (int k0 = 0; k0 < K; k0 += 8) {
        float4 av = *(const float4*)(Ap + k0);
        float4 bv = *(const float4*)(Bp + k0);
        As[lc+0][lr] = av.x; As[lc+1][lr] = av.y;
        As[lc+2][lr] = av.z; As[lc+3][lr] = av.w;
        Bs[lc+0][lr] = bv.x; Bs[lc+1][lr] = bv.y;
        Bs[lc+2][lr] = bv.z; Bs[lc+3][lr] = bv.w;
        __syncthreads();
        #pragma unroll
        for (int kk = 0; kk < 8; kk++) {
            ulonglong2 A01 = *(const ulonglong2*)&As[kk][ty*8];
            ulonglong2 A23 = *(const ulonglong2*)&As[kk][ty*8+4];
            float4 b0 = *(const float4*)&Bs[kk][tx*8];
            float4 b1 = *(const float4*)&Bs[kk][tx*8+4];
            unsigned long long a2[4] = {A01.x, A01.y, A23.x, A23.y};
            unsigned long long bsp[8] = {
                splat2(b0.x), splat2(b0.y), splat2(b0.z), splat2(b0.w),
                splat2(b1.x), splat2(b1.y), splat2(b1.z), splat2(b1.w)};
            #pragma unroll
            for (int i2 = 0; i2 < 4; i2++)
                #pragma unroll
                for (int j = 0; j < 8; j++)
                    acc2[i2][j] = ffma2(a2[i2], bsp[j], acc2[i2][j]);
        }
        __syncthreads();
    }

    #pragma unroll
    for (int i2 = 0; i2 < 4; i2++) {
        int m0 = bm + ty*8 + i2*2;       // even
        #pragma unroll
        for (int j = 0; j < 8; j++) {
            int n = bn + tx*8 + j;
            float2 v = unpack2(acc2[i2][j]);
            float bb = bias[n];
            float v0 = v.x + bb, v1 = v.y + bb;
            if (ACT) { v0 = (v0 > 1e-6f) ? v0 : 0.0f;
                       v1 = (v1 > 1e-6f) ? v1 : 0.0f; }
            if (TRANSOUT) {
                int s = m0 >> 6, b0 = m0 & 63;   // m0 even -> m0,m0+1 same s
                float2 p; p.x = v0; p.y = v1;
                *(float2*)&C[((size_t)s * N + n) * 64 + b0] = p;
            } else {
                C[(size_t)m0     * N + n] = v0;
                C[(size_t)(m0+1) * N + n] = v1;
            }
        }
    }
}

// ---------------- tree grid barrier (2-level, graph-replay safe) ----------
__device__ __forceinline__ void grid_bar()
{
    __threadfence();
    __syncthreads();
    if (threadIdx.x == 0) {
        unsigned my = g_gen;
        int leaf = blockIdx.x & 15;               // 16 leaves x 8 blocks
        bool done = false;
        if (atomicAdd(&g_leaf[leaf*32], 1) == 7) {
            g_leaf[leaf*32] = 0;
            __threadfence();
            if (atomicAdd(&g_root, 1) == 15) {
                g_root = 0;
                __threadfence();
                g_gen = my + 1;
                done = true;
            }
        }
        if (!done) { while (g_gen == my) { } }
    }
    __syncthreads();
}

// ---------------- 3) persistent GRU recurrence ----------------------------
// 128 blocks x 1024 threads (32 warps/SM, 1 block/SM via smem). Block owns
// 8 h-columns = 24 W_hh rows in smem (stride-32 rows: LDS.128 w-triples).
// 8 k-groups x 128 threads; per group: 8 k-tiles of 16, double-buffered
// LDG.128->STS.128 staging, per-group named barriers. Each thread: 4
// batches x 3 gate-cols, f32x2 FMAs. xw is [S][3H][B] -> coalesced gates.
#define WSM_F   (1024*32)          // Wsm[k*32 + tc*4 + j]
#define HSS_F   (2*8*16*68)        // Hs[buf][g][k][b] = 17408 floats
#define SMEM_BYTES ((WSM_F + HSS_F) * 4)   // 200704 B

__global__ void __launch_bounds__(GNT, 1)
gru_persist(const float* __restrict__ W_hh, const float* __restrict__ b_hh,
            const float* __restrict__ xw, float* __restrict__ hbuf)
{
    extern __shared__ float smf[];
    float* Wsm = smf;                    // 32768 floats
    float* Hss = smf + WSM_F;            // 17408 floats
    float* red = Hss;                    // alias: 8*1600 = 12800 floats

    const int tid = threadIdx.x;
    const int g   = tid >> 7;            // k-group 0..7 (128 k each)
    const int t   = tid & 127;
    const int tb  = t >> 3;              // batch-group 0..15 (4 batches)
    const int tc  = t & 7;               // c-group 0..7 (c = tc*3+j)
    const int j0  = blockIdx.x * 8;

    // cache W_hh slice: Wsm[k*32 + (c/3)*4 + c%3]
    for (int idx = tid; idx < 24*1024; idx += GNT) {
        int c = idx >> 10, k = idx & 1023;
        int grow = (c >> 3) * HH + j0 + (c & 7);
        Wsm[k*32 + (c/3)*4 + (c%3)] = W_hh[(size_t)grow * HH + k];
    }

    // gate-phase mapping (tid < 512): jj slow, bb fast -> coalesced
    const int jj   = (tid >> 6) & 7;
    const int bb   = tid & 63;
    const int jcol = j0 + jj;
    float bhr = 0.f, bhz = 0.f, bhn = 0.f;
    if (tid < 512) {
        bhr = b_hh[jcol];
        bhz = b_hh[HH + jcol];
        bhn = b_hh[2*HH + jcol];
    }
    __syncthreads();

    for (int s = 0; s < SS; s++) {
        const float* h_in  = hbuf + (s & 1) * (HH*BB);
        float*       h_out = hbuf + ((s + 1) & 1) * (HH*BB);
        const float* xws   = xw + (size_t)s * G3 * BB;   // [3H][B]

        float xr = 0.f, xz = 0.f, xn = 0.f;
        float hp = 0.f, gr = 0.f, gz = 0.f, gn = 0.f;

        if (s > 0) {
            unsigned long long acc2[2][3];
            #pragma unroll
            for (int i = 0; i < 2; i++)
                #pragma unroll
                for (int j = 0; j < 3; j++) acc2[i][j] = 0ULL;

            // prologue: prefetch kt=0 tile (coalesced: h_in is [k][b])
            float4 pre[2];
            {
                int kb = g * 128;
                #pragma unroll
                for (int r = 0; r < 2; r++) {
                    int f = t + 128*r;           // 0..255
                    int k = kb + (f >> 4), b4 = (f & 15) * 4;
                    pre[r] = __ldcg((const float4*)&h_in[(size_t)k*BB + b4]);
                }
            }

            for (int kt = 0; kt < 8; kt++) {
                float* Hbuf = Hss + (((kt & 1) * 8 + g) * 16) * 68;
                #pragma unroll
                for (int r = 0; r < 2; r++) {
                    int f = t + 128*r;
                    int kk2 = f >> 4, b4 = (f & 15) * 4;
                    *(float4*)&Hbuf[kk2*68 + b4] = pre[r];
                }
                asm volatile("bar.sync %0, 128;" :: "r"(1 + g) : "memory");
                if (kt < 7) {
                    int kb = g * 128 + (kt + 1) * 16;
                    #pragma unroll
                    for (int r = 0; r < 2; r++) {
                        int f = t + 128*r;
                        int k = kb + (f >> 4), b4 = (f & 15) * 4;
                        pre[r] = __ldcg((const float4*)&h_in[(size_t)k*BB + b4]);
                    }
                }
                const float* wbase = Wsm + (g*128 + kt*16) * 32 + tc*4;
                #pragma unroll
                for (int kk = 0; kk < 16; kk++) {
                    const float* hrow = Hbuf + kk*68;
                    ulonglong2 hA = *(const ulonglong2*)&hrow[tb*4];
                    float4 wv = *(const float4*)(wbase + kk*32);
                    unsigned long long w0 = splat2(wv.x);
                    unsigned long long w1 = splat2(wv.y);
                    unsigned long long w2 = splat2(wv.z);
                    acc2[0][0] = ffma2(hA.x, w0, acc2[0][0]);
                    acc2[0][1] = ffma2(hA.x, w1, acc2[0][1]);
                    acc2[0][2] = ffma2(hA.x, w2, acc2[0][2]);
                    acc2[1][0] = ffma2(hA.y, w0, acc2[1][0]);
                    acc2[1][1] = ffma2(hA.y, w1, acc2[1][1]);
                    acc2[1][2] = ffma2(hA.y, w2, acc2[1][2]);
                }
            }

            // gate-input prefetch (coalesced; covered by reduce phase)
            if (tid < 512) {
                xr = __ldg(&xws[(size_t)jcol*BB + bb]);
                xz = __ldg(&xws[(size_t)(HH + jcol)*BB + bb]);
                xn = __ldg(&xws[(size_t)(2*HH + jcol)*BB + bb]);
                hp = __ldcg(&h_in[(size_t)jcol*BB + bb]);
            }

            // parallel 8-way tree reduction (partials alias Hss)
            __syncthreads();   // all groups done with Hss; reusable
            {
                float* myred = red + g * 1600;
                #pragma unroll
                for (int i2 = 0; i2 < 2; i2++) {
                    int b = tb*4 + i2*2;
                    #pragma unroll
                    for (int j = 0; j < 3; j++) {
                        float2 v = unpack2(acc2[i2][j]);
                        int c = tc*3 + j;
                        myred[b*25 + c]     = v.x;
                        myred[(b+1)*25 + c] = v.y;
                    }
                }
            }
            __syncthreads();
            for (int o = tid; o < 1600; o += GNT) {
                float sum = red[o];
                #pragma unroll
                for (int gg = 1; gg < 8; gg++) sum += red[gg*1600 + o];
                red[o] = sum;
            }
            __syncthreads();
            if (tid < 512) {
                gr = red[bb*25 + jj];
                gz = red[bb*25 + 8 + jj];
                gn = red[bb*25 + 16 + jj];
            }
        } else {
            if (tid < 512) {
                xr = __ldg(&xws[(size_t)jcol*BB + bb]);
                xz = __ldg(&xws[(size_t)(HH + jcol)*BB + bb]);
                xn = __ldg(&xws[(size_t)(2*HH + jcol)*BB + bb]);
            }
        }

        // fused gates + h update (coalesced transposed store)
        if (tid < 512) {
            float r = 1.0f / (1.0f + __expf(-(xr + gr + bhr)));
            float z = 1.0f / (1.0f + __expf(-(xz + gz + bhz)));
            float n = tanhf(xn + r * (gn + bhn));
            __stcg(&h_out[(size_t)jcol*BB + bb], (1.0f - z) * n + z * hp);
        }

        grid_bar();
    }
}

// ---------------- 4) final linear: out[b][n] = sum_k h[k][b]*Wo[n][k] -----
__global__ void __launch_bounds__(256)
out_kernel(const float* __restrict__ h /* [HH][BB] */,
           const float* __restrict__ Wo,
           const float* __restrict__ bo, float* __restrict__ out)
{
    __shared__ float hs[8][1032];        // [bb][k], padded stride
    const int b0 = blockIdx.x * 8;
    const int n0 = blockIdx.y * 8;
    const int tid = threadIdx.x;

    for (int idx = tid; idx < 8192; idx += 256) {
        int k = idx >> 3, bb = idx & 7;
        hs[bb][k] = h[(size_t)k*BB + b0 + bb];
    }
    __syncthreads();

    const int w = tid >> 5, lane = tid & 31;
    const int n = n0 + w;
    float acc[8] = {0,0,0,0,0,0,0,0};
    for (int k = lane*4; k < 1024; k += 128) {
        float4 wv = *(const float4*)&Wo[(size_t)n*HH + k];
        #pragma unroll
        for (int bb = 0; bb < 8; bb++) {
            float4 hv = *(const float4*)&hs[bb][k];
            acc[bb] += wv.x*hv.x + wv.y*hv.y + wv.z*hv.z + wv.w*hv.w;
        }
    }
    #pragma unroll
    for (int bb = 0; bb < 8; bb++) {
        float v = acc[bb];
        v += __shfl_down_sync(0xffffffffu, v, 16);
        v += __shfl_down_sync(0xffffffffu, v, 8);
        v += __shfl_down_sync(0xffffffffu, v, 4);
        v += __shfl_down_sync(0xffffffffu, v, 2);
        v += __shfl_down_sync(0xffffffffu, v, 1);
        if (lane == 0) out[(size_t)(b0+bb)*1024 + n] = v + bo[n];
    }
}

// ---------------- launch ----------------
extern "C" void kernel_launch(void* const* d_in, const int* in_sizes, int n_in,
                              void* d_out, int out_size)
{
    const int*   ids   = (const int*)  d_in[0];
    const float* W1    = (const float*)d_in[1];
    const float* b1    = (const float*)d_in[2];
    const float* W2    = (const float*)d_in[3];
    const float* b2    = (const float*)d_in[4];
    const float* W_ih  = (const float*)d_in[5];
    const float* b_ih  = (const float*)d_in[6];
    const float* W_hh  = (const float*)d_in[7];
    const float* b_hh  = (const float*)d_in[8];
    const float* W_out = (const float*)d_in[9];
    const float* b_out = (const float*)d_in[10];
    float* out = (float*)d_out;

    float* emb;  cudaGetSymbolAddress((void**)&emb,  g_emb);
    float* x;    cudaGetSymbolAddress((void**)&x,    g_x);
    float* xw;   cudaGetSymbolAddress((void**)&xw,   g_xw);
    float* hbuf; cudaGetSymbolAddress((void**)&hbuf, g_h);

    static int smem_set = 0;
    if (!smem_set) {
        cudaFuncSetAttribute(gru_persist,
                             cudaFuncAttributeMaxDynamicSharedMemorySize,
                             SMEM_BYTES);
        smem_set = 1;
    }

    emb_kernel<<<TOK, 128>>>(ids, W1, b1);

    gemm_nt_act<1,0><<<dim3(EOO/128, TOK/128), 256>>>(emb, W2, b2, x, TOK, EOO, EHH);
    gemm_nt_act<0,1><<<dim3(G3/128,  TOK/128), 256>>>(x, W_ih, b_ih, xw, TOK, G3, EOO);

    gru_persist<<<NB, GNT, SMEM_BYTES>>>(W_hh, b_hh, xw, hbuf);

    out_kernel<<<dim3(8, 128), 256>>>(hbuf, W_out, b_out, out);
}